// round 1
// baseline (speedup 1.0000x reference)
#include <cuda_runtime.h>

#define NN 8192
#define KK 64
#define DD 256
#define HH 128

// ---- flat fp32 output layout (concat of reference tuple) ----
#define OFF_ADJ    0LL
#define OFF_FEAT   ((long long)NN * NN)
#define OFF_PROB   (OFF_FEAT + (long long)NN * DD)
#define OFF_PAIR   (OFF_PROB + (long long)NN * KK * 2)
#define OFF_BEFORE (OFF_PAIR + (long long)NN * KK * 2)
#define OFF_AFTER  (OFF_BEFORE + 1)
#define OFF_LEFT   (OFF_AFTER + 1)

// scratch: featW = feat @ W1   [N, 128]  (4 MB)
__device__ float g_featW[(size_t)NN * HH];

// ---------------------------------------------------------------------------
// Kernel 1: featW = feat @ W1  (no bias; b1 added on the src side later so it
// survives the src-dst subtraction exactly like the reference).
// One warp per row; each lane accumulates 4 output columns (float4).
// ---------------------------------------------------------------------------
__global__ void __launch_bounds__(256) featw_kernel(const float* __restrict__ feat,
                                                    const float* __restrict__ W1,
                                                    float* __restrict__ out) {
    __shared__ float srow[8][DD];
    const int warp = threadIdx.x >> 5;
    const int lane = threadIdx.x & 31;
    const int row  = blockIdx.x * 8 + warp;

    // load this warp's feat row (256 floats) into shared
    const float4* f4 = reinterpret_cast<const float4*>(feat + (size_t)row * DD);
    float4* s4 = reinterpret_cast<float4*>(&srow[warp][0]);
    s4[lane]      = f4[lane];
    s4[lane + 32] = f4[lane + 32];
    __syncwarp();

    const float4* W14 = reinterpret_cast<const float4*>(W1);  // [256][32] float4
    float4 acc = make_float4(0.f, 0.f, 0.f, 0.f);
#pragma unroll 4
    for (int k = 0; k < DD; k++) {
        float s = srow[warp][k];
        float4 wv = W14[k * 32 + lane];
        acc.x = fmaf(s, wv.x, acc.x);
        acc.y = fmaf(s, wv.y, acc.y);
        acc.z = fmaf(s, wv.z, acc.z);
        acc.w = fmaf(s, wv.w, acc.w);
    }
    reinterpret_cast<float4*>(g_featW + (size_t)row * HH)[lane] = acc;

    if (blockIdx.x == 0 && threadIdx.x == 0) {
        out[OFF_BEFORE] = 64.0f;   // E / dst == K
        out[OFF_AFTER]  = 0.0f;    // accumulated by edge_kernel atomics
    }
}

// ---------------------------------------------------------------------------
// Kernel 2: one block per dst row (8192 blocks x 256 threads).
//   A) per-edge MLP head: h = featW[src]+b1 - featW[dst]; PReLU; 128x2 GEMV;
//      softmax -> prob_arr, pair_list. One warp per edge, 8 edges at a time.
//   B) stable ascending rank of p1 over the row's 64 edges (O(K^2), exact
//      match for stable jnp.argsort). rank>=32 -> kept.
//   C) gather adj values for kept edges, degree sum, left_row, nonzero count.
//   D) zero-fill the 32KB output row, then scatter kept val/(deg+1e-6).
// ---------------------------------------------------------------------------
__global__ void __launch_bounds__(256) edge_kernel(const float* __restrict__ adj,
                                                   const int*   __restrict__ nbr,
                                                   const float* __restrict__ b1,
                                                   const float* __restrict__ prelu_a,
                                                   const float* __restrict__ W2,
                                                   const float* __restrict__ b2,
                                                   float* __restrict__ out) {
    __shared__ __align__(16) float sfw[HH];
    __shared__ float sp1[KK];
    __shared__ int   snbr[KK];
    __shared__ float sred[KK];
    __shared__ float scnt[KK];
    __shared__ float sdeg;

    const int row  = blockIdx.x;
    const int tid  = threadIdx.x;
    const int lane = tid & 31;
    const int warp = tid >> 5;

    if (tid < HH) sfw[tid] = g_featW[(size_t)row * HH + tid] + b1[tid];
    if (tid < KK) snbr[tid] = nbr[row * KK + tid];
    __syncthreads();

    // per-lane loop invariants (4 feature dims per lane)
    const float4 fs = reinterpret_cast<const float4*>(sfw)[lane];
    const int j0 = lane * 4;
    const float a0 = prelu_a[j0 + 0], a1 = prelu_a[j0 + 1],
                a2 = prelu_a[j0 + 2], a3 = prelu_a[j0 + 3];
    const float w00 = W2[(j0 + 0) * 2],     w01 = W2[(j0 + 0) * 2 + 1];
    const float w10 = W2[(j0 + 1) * 2],     w11 = W2[(j0 + 1) * 2 + 1];
    const float w20 = W2[(j0 + 2) * 2],     w21 = W2[(j0 + 2) * 2 + 1];
    const float w30 = W2[(j0 + 3) * 2],     w31 = W2[(j0 + 3) * 2 + 1];
    const float bb0 = b2[0], bb1 = b2[1];

    const float4* fW4 = reinterpret_cast<const float4*>(g_featW);

#pragma unroll
    for (int e = 0; e < 8; e++) {
        const int k   = e * 8 + warp;       // edge column within the row
        const int dst = snbr[k];
        float4 fd = fW4[(size_t)dst * 32 + lane];   // gathered 512B per warp
        float h0 = fs.x - fd.x, h1 = fs.y - fd.y;
        float h2 = fs.z - fd.z, h3 = fs.w - fd.w;
        h0 = (h0 >= 0.f) ? h0 : a0 * h0;
        h1 = (h1 >= 0.f) ? h1 : a1 * h1;
        h2 = (h2 >= 0.f) ? h2 : a2 * h2;
        h3 = (h3 >= 0.f) ? h3 : a3 * h3;
        float l0 = h0 * w00 + h1 * w10 + h2 * w20 + h3 * w30;
        float l1 = h0 * w01 + h1 * w11 + h2 * w21 + h3 * w31;
#pragma unroll
        for (int off = 16; off; off >>= 1) {
            l0 += __shfl_xor_sync(0xffffffffu, l0, off);
            l1 += __shfl_xor_sync(0xffffffffu, l1, off);
        }
        if (lane == 0) {
            l0 += bb0; l1 += bb1;
            float m  = fmaxf(l0, l1);
            float e0 = expf(l0 - m), e1 = expf(l1 - m);
            float inv = 1.0f / (e0 + e1);
            float p0 = e0 * inv, p1 = e1 * inv;
            long long eid = (long long)row * KK + k;
            reinterpret_cast<float2*>(out + OFF_PROB)[eid] = make_float2(p0, p1);
            reinterpret_cast<float2*>(out + OFF_PAIR)[eid] =
                make_float2((float)row, (float)dst);
            sp1[k] = p1;
        }
    }
    __syncthreads();

    // stable ascending rank (== stable argsort position)
    float val = 0.f;
    int   keep = 0;
    if (tid < KK) {
        const float mine = sp1[tid];
        int rank = 0;
#pragma unroll 8
        for (int j = 0; j < KK; j++) {
            float pj = sp1[j];
            rank += (pj < mine) || (pj == mine && j < tid);
        }
        if (rank >= 32) {                              // kept edge
            keep = 1;
            val = __ldg(adj + (size_t)row * NN + snbr[tid]);
            out[OFF_LEFT + (long long)row * 32 + (rank - 32)] =
                (float)(row * KK + tid);
        }
        sred[tid] = val;
        scnt[tid] = (keep && val != 0.f) ? 1.f : 0.f;
    }
    __syncthreads();

    if (tid < 32) {
        float v = sred[tid] + sred[tid + 32];
        float c = scnt[tid] + scnt[tid + 32];
#pragma unroll
        for (int off = 16; off; off >>= 1) {
            v += __shfl_xor_sync(0xffffffffu, v, off);
            c += __shfl_xor_sync(0xffffffffu, c, off);
        }
        if (tid == 0) {
            sdeg = v;
            atomicAdd(out + OFF_AFTER, c * (1.0f / 8192.0f)); // exact multiples of 2^-8
        }
    }

    // zero-fill this output row (2048 float4 = 32KB), overlaps DRAM writes
    float4* orow = reinterpret_cast<float4*>(out + (size_t)row * NN);
    const float4 z = make_float4(0.f, 0.f, 0.f, 0.f);
#pragma unroll
    for (int i = 0; i < 8; i++) orow[i * 256 + tid] = z;
    __syncthreads();   // order zero-fill before scatter (and publish sdeg)

    if (keep) {
        out[(size_t)row * NN + snbr[tid]] = val / (sdeg + 1e-6f);
    }
}

// ---------------------------------------------------------------------------
extern "C" void kernel_launch(void* const* d_in, const int* in_sizes, int n_in,
                              void* d_out, int out_size) {
    const float* adj = nullptr; const float* feat = nullptr;
    const int*   nbr = nullptr; const float* W1   = nullptr;
    const float* b1  = nullptr; const float* pa   = nullptr;
    const float* W2  = nullptr; const float* b2   = nullptr;

    for (int i = 0; i < n_in; i++) {
        long long s = in_sizes[i];
        if      (s == (long long)NN * NN) adj  = (const float*)d_in[i];
        else if (s == (long long)NN * DD) feat = (const float*)d_in[i];
        else if (s == (long long)NN * KK) nbr  = (const int*)d_in[i];
        else if (s == (long long)DD * HH) W1   = (const float*)d_in[i];
        else if (s == HH) { if (!b1) b1 = (const float*)d_in[i];
                            else     pa = (const float*)d_in[i]; }
        else if (s == HH * 2) W2 = (const float*)d_in[i];
        else if (s == 2)      b2 = (const float*)d_in[i];
        // size-1 dst_num ignored (shapes are compile-time constants)
    }

    float* out = (float*)d_out;
    featw_kernel<<<NN / 8, 256>>>(feat, W1, out);
    edge_kernel<<<NN, 256>>>(adj, nbr, b1, pa, W2, b2, out);
    cudaMemcpyAsync(out + OFF_FEAT, feat, (size_t)NN * DD * sizeof(float),
                    cudaMemcpyDeviceToDevice, 0);
}